// round 3
// baseline (speedup 1.0000x reference)
#include <cuda_runtime.h>
#include <cuda_bf16.h>

#define NMAX 4096
#define BIGF 1e30f
#define TILE 128

// Scratch (__device__ globals; allocation is forbidden)
__device__ unsigned int g_d1[NMAX];   // min over m1 rows, per column j (float bits)
__device__ unsigned int g_d2[NMAX];   // min over m2 cols, per row i    (float bits)
__device__ unsigned int g_ctr = 0;    // last-block-done counter (self-resetting)

// ---------------- packed f32x2 helpers (SASS FFMA2/FADD2 path) ----------------
__device__ __forceinline__ unsigned long long f2pack(float lo, float hi) {
    unsigned long long r;
    asm("mov.b64 %0, {%1, %2};" : "=l"(r) : "f"(lo), "f"(hi));
    return r;
}
__device__ __forceinline__ void f2unpack(unsigned long long v, float& lo, float& hi) {
    asm("mov.b64 {%0, %1}, %2;" : "=f"(lo), "=f"(hi) : "l"(v));
}
__device__ __forceinline__ unsigned long long f2add(unsigned long long a, unsigned long long b) {
    unsigned long long r;
    asm("add.rn.f32x2 %0, %1, %2;" : "=l"(r) : "l"(a), "l"(b));
    return r;
}
__device__ __forceinline__ unsigned long long f2mul(unsigned long long a, unsigned long long b) {
    unsigned long long r;
    asm("mul.rn.f32x2 %0, %1, %2;" : "=l"(r) : "l"(a), "l"(b));
    return r;
}
__device__ __forceinline__ unsigned long long f2fma(unsigned long long a, unsigned long long b,
                                                    unsigned long long c) {
    unsigned long long r;
    asm("fma.rn.f32x2 %0, %1, %2, %3;" : "=l"(r) : "l"(a), "l"(b), "l"(c));
    return r;
}

// ---------------------------------------------------------------------------
// Fused kernel: inline prep + tiled masked-min distances + last-block reduce.
// 128x128 tile per block, 256 threads (16x16), micro-tile 8 rows x 8 cols
// (columns processed as 4 packed f32x2 pairs).
// ---------------------------------------------------------------------------
__global__ void __launch_bounds__(256) fused_kernel(const float* __restrict__ norm,
                                                    const float* __restrict__ pts,
                                                    float* __restrict__ out,
                                                    int n, int nblocks) {
    __shared__ float4 sr[TILE];          // reflected rows + rp (m1?0:BIG)
    __shared__ float4 sc[TILE];          // NEGATED cols + cp (m2?0:BIG)
    __shared__ unsigned int credu[TILE];
    __shared__ unsigned int rredu[TILE];
    __shared__ int slast;
    __shared__ float sred[4][8];

    int t = threadIdx.x;
    int i0 = blockIdx.y * TILE;
    int j0 = blockIdx.x * TILE;

    float nx = __ldg(norm), ny = __ldg(norm + 1), nz = __ldg(norm + 2), dd = __ldg(norm + 3);
    float nn = nx * nx + ny * ny + nz * nz;

    // ---- inline prep into smem ----
    if (t < TILE) {
        int gi = i0 + t;
        float4 v = make_float4(0.f, 0.f, 0.f, BIGF);
        if (gi < n) {
            float px = pts[3 * gi], py = pts[3 * gi + 1], pz = pts[3 * gi + 2];
            float ts = -2.0f * (px * nx + py * ny + pz * nz + dd);
            float k = ts / nn;
            v = make_float4(fmaf(k, nx, px), fmaf(k, ny, py), fmaf(k, nz, pz),
                            ts > 0.0f ? 0.0f : BIGF);
        }
        sr[t] = v;
        credu[t] = __float_as_uint(BIGF);
    } else {
        int u = t - TILE;
        int gj = j0 + u;
        float4 v = make_float4(0.f, 0.f, 0.f, BIGF);
        if (gj < n) {
            float px = pts[3 * gj], py = pts[3 * gj + 1], pz = pts[3 * gj + 2];
            float ts = -2.0f * (px * nx + py * ny + pz * nz + dd);
            v = make_float4(-px, -py, -pz, ts > 0.0f ? BIGF : 0.0f);  // negated!
        }
        sc[u] = v;
        rredu[u] = __float_as_uint(BIGF);
    }
    __syncthreads();

    int tx = t & 15, ty = t >> 4;

    // rows: scalar registers
    float rx[8], ry[8], rz[8], rp[8];
#pragma unroll
    for (int r = 0; r < 8; r++) {
        float4 v = sr[ty * 8 + r];
        rx[r] = v.x; ry[r] = v.y; rz[r] = v.z; rp[r] = v.w;
    }
    // cols: packed pairs; pair k covers local cols k*32 + 2*tx + {0,1}
    unsigned long long ncx[4], ncy[4], ncz[4], cp2[4];
#pragma unroll
    for (int k = 0; k < 8; k += 2) {
        float4 a = sc[(k >> 1) * 32 + 2 * tx];
        float4 b = sc[(k >> 1) * 32 + 2 * tx + 1];
        ncx[k >> 1] = f2pack(a.x, b.x);
        ncy[k >> 1] = f2pack(a.y, b.y);
        ncz[k >> 1] = f2pack(a.z, b.z);
        cp2[k >> 1] = f2pack(a.w, b.w);
    }

    float cmin[8], rmin[8];
#pragma unroll
    for (int k = 0; k < 8; k++) { cmin[k] = BIGF; rmin[k] = BIGF; }

#pragma unroll
    for (int r = 0; r < 8; r++) {
        unsigned long long rxx = f2pack(rx[r], rx[r]);
        unsigned long long ryy = f2pack(ry[r], ry[r]);
        unsigned long long rzz = f2pack(rz[r], rz[r]);
        unsigned long long rpp = f2pack(rp[r], rp[r]);
#pragma unroll
        for (int k = 0; k < 4; k++) {
            unsigned long long dx = f2add(rxx, ncx[k]);       // r - c (cols negated)
            unsigned long long dy = f2add(ryy, ncy[k]);
            unsigned long long dz = f2add(rzz, ncz[k]);
            unsigned long long D  = f2mul(dx, dx);
            D = f2fma(dy, dy, D);
            D = f2fma(dz, dz, D);
            unsigned long long Dr = f2add(D, rpp);            // + row penalty -> col mins
            unsigned long long Dc = f2add(D, cp2[k]);         // + col penalty -> row mins
            float a, b;
            f2unpack(Dr, a, b);
            cmin[2 * k]     = fminf(cmin[2 * k], a);
            cmin[2 * k + 1] = fminf(cmin[2 * k + 1], b);
            f2unpack(Dc, a, b);
            rmin[r] = fminf(rmin[r], fminf(a, b));
        }
    }

    // ---- block-local min reduction ----
#pragma unroll
    for (int k = 0; k < 4; k++) {
        atomicMin(&credu[k * 32 + 2 * tx],     __float_as_uint(cmin[2 * k]));
        atomicMin(&credu[k * 32 + 2 * tx + 1], __float_as_uint(cmin[2 * k + 1]));
    }
#pragma unroll
    for (int r = 0; r < 8; r++)
        atomicMin(&rredu[ty * 8 + r], __float_as_uint(rmin[r]));
    __syncthreads();

    if (t < TILE) {
        int gj = j0 + t;
        if (gj < n) atomicMin(&g_d1[gj], credu[t]);
    } else {
        int u = t - TILE;
        int gi = i0 + u;
        if (gi < n) atomicMin(&g_d2[gi], rredu[u]);
    }

    // ---- last-block finalize ----
    __threadfence();
    __syncthreads();
    if (t == 0)
        slast = (atomicInc(&g_ctr, (unsigned int)(nblocks - 1)) == (unsigned int)(nblocks - 1));
    __syncthreads();
    if (!slast) return;

    float s1 = 0.f, s2 = 0.f, c1 = 0.f, c2 = 0.f;
    for (int i = t; i < n; i += 256) {
        float px = pts[3 * i], py = pts[3 * i + 1], pz = pts[3 * i + 2];
        float ts = -2.0f * (px * nx + py * ny + pz * nz + dd);
        float d1v = __uint_as_float(g_d1[i]);
        float d2v = __uint_as_float(g_d2[i]);
        if (ts > 0.0f) { s2 += d2v; c1 += 1.0f; }   // m1 rows -> av2 terms
        else           { s1 += d1v; c2 += 1.0f; }   // m2 cols -> av1 terms
    }
#pragma unroll
    for (int o = 16; o > 0; o >>= 1) {
        s1 += __shfl_xor_sync(0xffffffffu, s1, o);
        s2 += __shfl_xor_sync(0xffffffffu, s2, o);
        c1 += __shfl_xor_sync(0xffffffffu, c1, o);
        c2 += __shfl_xor_sync(0xffffffffu, c2, o);
    }
    int w = t >> 5, l = t & 31;
    if (l == 0) { sred[0][w] = s1; sred[1][w] = s2; sred[2][w] = c1; sred[3][w] = c2; }
    __syncthreads();
    if (t == 0) {
        float S1 = 0.f, S2 = 0.f, C1 = 0.f, C2 = 0.f;
#pragma unroll
        for (int i = 0; i < 8; i++) {
            S1 += sred[0][i]; S2 += sred[1][i]; C1 += sred[2][i]; C2 += sred[3][i];
        }
        C1 = fmaxf(C1, 1.0f);
        C2 = fmaxf(C2, 1.0f);
        out[0] = (0.5f * (S1 / C2) + 0.5f * (S2 / C1)) * 100.0f;
    }
}

// ---------------------------------------------------------------------------
extern "C" void kernel_launch(void* const* d_in, const int* in_sizes, int n_in,
                              void* d_out, int out_size) {
    const float* a0 = (const float*)d_in[0];
    const float* a1 = (const float*)d_in[1];
    const float* norm;
    const float* pts;
    int n;
    if (in_sizes[0] == 4) { norm = a0; pts = a1; n = in_sizes[1] / 3; }
    else                  { norm = a1; pts = a0; n = in_sizes[0] / 3; }

    float* out = (float*)d_out;

    // init min arrays to "+inf" (0x7F7F7F7F = 3.39e38 > any D + 1e30 penalty)
    void* p1 = nullptr; void* p2 = nullptr;
    cudaGetSymbolAddress(&p1, g_d1);
    cudaGetSymbolAddress(&p2, g_d2);
    cudaMemsetAsync(p1, 0x7F, (size_t)n * sizeof(unsigned int), 0);
    cudaMemsetAsync(p2, 0x7F, (size_t)n * sizeof(unsigned int), 0);

    int nt = (n + TILE - 1) / TILE;
    dim3 grid(nt, nt);
    fused_kernel<<<grid, 256>>>(norm, pts, out, n, nt * nt);
}